// round 2
// baseline (speedup 1.0000x reference)
#include <cuda_runtime.h>
#include <cstdint>
#include <cstring>

#define Nn 32768
#define Dd 512
#define Cc 64
#define Kk 16
#define Mm 512
#define Jj 256   // C*DEPTH

// ---------------- scratch (no allocations allowed) ----------------
__device__ float d_Lt[Cc * Kk * Mm];            // [c][k][m]  2 MB
__device__ unsigned char d_idxT[Cc * Nn];       // [c][n]     2 MB (transposed)

// ---------------- K0: transpose L (M,C,K) -> Lt (C*K, M) ----------------
__global__ void k_transpose(const float* __restrict__ L) {
    __shared__ float tile[32][33];
    int bx = blockIdx.x * 32;   // ck
    int by = blockIdx.y * 32;   // m
    for (int i = threadIdx.y; i < 32; i += 8)
        tile[i][threadIdx.x] = L[(size_t)(by + i) * (Cc * Kk) + bx + threadIdx.x];
    __syncthreads();
    for (int i = threadIdx.y; i < 32; i += 8)
        d_Lt[(size_t)(bx + i) * Mm + by + threadIdx.x] = tile[threadIdx.x][i];
}

// ---------------- K1: fused GEMM (P = I @ A) + tree traversal -> idxT ----------------
__device__ __forceinline__ unsigned trav(const float* __restrict__ Tc,
                                         float f0, float f1, float f2, float f3) {
    float f[4] = {f0, f1, f2, f3};
    unsigned node = 0, k = 0;
#pragma unroll
    for (int l = 0; l < 4; l++) {
        unsigned bit = (f[l] > __ldg(&Tc[node])) ? 1u : 0u;
        k = (k << 1) | bit;
        node = 2 * node + 1 + bit;
    }
    return k;
}

#define BM 128
#define BN 128
#define BK 32

__global__ __launch_bounds__(256, 2) void k_gemm_tree(
    const float* __restrict__ I, const float* __restrict__ A,
    const float* __restrict__ T)
{
    __shared__ float Is[BK][132];   // k-major, padded
    __shared__ float As[BK][BN];    // k-major

    int tid = threadIdx.x;
    int tx = tid & 15;
    int ty = tid >> 4;
    int rowBase = blockIdx.y * BM;
    int colBase = blockIdx.x * BN;

    // global-load lane mapping
    int r  = tid >> 3;   // 0..31 (I row group)
    int kv = tid & 7;    // float4 along k
    int kk = tid >> 5;   // 0..7  (A k row group)
    int jv = tid & 31;   // float4 along j

    unsigned long long acc[8][4];   // 8 rows x 4 j-pairs (f32x2)
#pragma unroll
    for (int i = 0; i < 8; i++)
#pragma unroll
        for (int j = 0; j < 4; j++) acc[i][j] = 0ull;

    float4 rI[4], rA[4];
    // preload tile 0
#pragma unroll
    for (int q = 0; q < 4; q++)
        rI[q] = *(const float4*)&I[(size_t)(rowBase + r + q * 32) * Dd + kv * 4];
#pragma unroll
    for (int q = 0; q < 4; q++)
        rA[q] = *(const float4*)&A[(size_t)(kk + q * 8) * Jj + colBase + jv * 4];

    for (int kt = 0; kt < Dd; kt += BK) {
        // store staged regs into smem
#pragma unroll
        for (int q = 0; q < 4; q++) {
            int lr = r + q * 32;
            Is[kv * 4 + 0][lr] = rI[q].x;
            Is[kv * 4 + 1][lr] = rI[q].y;
            Is[kv * 4 + 2][lr] = rI[q].z;
            Is[kv * 4 + 3][lr] = rI[q].w;
        }
#pragma unroll
        for (int q = 0; q < 4; q++)
            *(float4*)&As[kk + q * 8][jv * 4] = rA[q];
        __syncthreads();

        // prefetch next tile while computing this one
        if (kt + BK < Dd) {
            int ktn = kt + BK;
#pragma unroll
            for (int q = 0; q < 4; q++)
                rI[q] = *(const float4*)&I[(size_t)(rowBase + r + q * 32) * Dd + ktn + kv * 4];
#pragma unroll
            for (int q = 0; q < 4; q++)
                rA[q] = *(const float4*)&A[(size_t)(ktn + kk + q * 8) * Jj + colBase + jv * 4];
        }

#pragma unroll 8
        for (int kx = 0; kx < BK; kx++) {
            // A fragment: 8 rows, broadcast across tx lanes (conflict-free)
            float4 a01 = *(const float4*)&Is[kx][ty * 8];
            float4 a23 = *(const float4*)&Is[kx][ty * 8 + 4];
            // B fragment: two float4 blocks 64 apart (conflict-free LDS.128),
            // naturally f32x2-packed column pairs
            ulonglong2 b0 = *(const ulonglong2*)&As[kx][tx * 4];
            ulonglong2 b1 = *(const ulonglong2*)&As[kx][64 + tx * 4];
            unsigned long long bp[4] = {b0.x, b0.y, b1.x, b1.y};
            float av[8] = {a01.x, a01.y, a01.z, a01.w, a23.x, a23.y, a23.z, a23.w};
#pragma unroll
            for (int i = 0; i < 8; i++) {
                unsigned long long ap;
                asm("mov.b64 %0, {%1, %2};" : "=l"(ap) : "f"(av[i]), "f"(av[i]));
#pragma unroll
                for (int j = 0; j < 4; j++)
                    asm("fma.rn.f32x2 %0, %1, %2, %0;"
                        : "+l"(acc[i][j]) : "l"(ap), "l"(bp[j]));
            }
        }
        __syncthreads();
    }

    // epilogue: thread owns codebooks cb0 = cbBase+tx, cb1 = cbBase+16+tx,
    // rows rowBase + ty*8 .. +7.  Pack 8 idx bytes per codebook -> 1 STG.64.
    int cbBase = colBase >> 2;
    int cb0 = cbBase + tx;
    int cb1 = cbBase + 16 + tx;
    unsigned long long p0 = 0, p1 = 0;
#pragma unroll
    for (int i = 0; i < 8; i++) {
        float f[8];
#pragma unroll
        for (int j = 0; j < 4; j++)
            asm("mov.b64 {%0, %1}, %2;" : "=f"(f[2 * j]), "=f"(f[2 * j + 1]) : "l"(acc[i][j]));
        unsigned k1 = trav(&T[cb0 * 15], f[0], f[1], f[2], f[3]);
        unsigned k2 = trav(&T[cb1 * 15], f[4], f[5], f[6], f[7]);
        p0 |= (unsigned long long)k1 << (8 * i);
        p1 |= (unsigned long long)k2 << (8 * i);
    }
    int nb = rowBase + ty * 8;
    *(unsigned long long*)&d_idxT[(size_t)cb0 * Nn + nb] = p0;
    *(unsigned long long*)&d_idxT[(size_t)cb1 * Nn + nb] = p1;
}

// ---------------- K3: LUT accumulate out[n,m] = sum_c Lt[c, idx[c,n], m] ----------------
#define K3_ROWS 256
#define K3_MT   32
#define K3_LS   (Cc * Kk * K3_MT)                 // floats: 32768 (128 KB)
#define K3_SMEM (K3_LS * 4 + Cc * K3_ROWS)        // + 16 KB idx = 147456

__global__ __launch_bounds__(256) void k_lut(float* __restrict__ out) {
    extern __shared__ char smraw[];
    float* Ls = (float*)smraw;                                  // [c][k][32m]
    unsigned char* idxs = (unsigned char*)(smraw + K3_LS * 4);  // [c][256 rows]

    int tid = threadIdx.x;
    int rowBase = blockIdx.y * K3_ROWS;
    int mBase   = blockIdx.x * K3_MT;

    // load Ls slice: 1024 rows of 32 floats
    for (int i = tid; i < Cc * Kk * (K3_MT / 4); i += 256) {
        int ck = i >> 3;
        int mv = i & 7;
        *(float4*)&Ls[ck * K3_MT + mv * 4] =
            *(const float4*)&d_Lt[(size_t)ck * Mm + mBase + mv * 4];
    }
    // load idx tile transposed: 64 c x 256 rows (u64 chunks, coalesced)
    for (int i = tid; i < Cc * K3_ROWS / 8; i += 256) {
        int c  = i >> 5;
        int r8 = i & 31;
        *(unsigned long long*)&idxs[c * K3_ROWS + r8 * 8] =
            *(const unsigned long long*)&d_idxT[(size_t)c * Nn + rowBase + r8 * 8];
    }
    __syncthreads();

    int mp = tid & 7;     // m-lane: 4 floats
    int rg = tid >> 3;    // row group 0..31 (8 rows each)
    int mOff = mp * 4;

    unsigned long long acc[8][2];
#pragma unroll
    for (int i = 0; i < 8; i++) { acc[i][0] = 0ull; acc[i][1] = 0ull; }

#pragma unroll 1
    for (int c8 = 0; c8 < 8; c8++) {
#pragma unroll
        for (int cc = 0; cc < 8; cc++) {
            int c = c8 * 8 + cc;
            // 8 rows' idx bytes for this c: broadcast LDS.64, conflict-free
            unsigned long long k8 = *(const unsigned long long*)&idxs[c * K3_ROWS + rg * 8];
            const float* Lc = &Ls[c * (Kk * K3_MT) + mOff];
#pragma unroll
            for (int i = 0; i < 8; i++) {
                unsigned k = (unsigned)(k8 >> (8 * i)) & 15u;
                ulonglong2 v = *(const ulonglong2*)&Lc[k * K3_MT];   // LDS.128, conflict-free
                asm("add.rn.f32x2 %0, %0, %1;" : "+l"(acc[i][0]) : "l"(v.x));
                asm("add.rn.f32x2 %0, %0, %1;" : "+l"(acc[i][1]) : "l"(v.y));
            }
        }
    }

#pragma unroll
    for (int i = 0; i < 8; i++) {
        int row = rowBase + rg * 8 + i;
        ulonglong2 st;
        st.x = acc[i][0];
        st.y = acc[i][1];
        *(ulonglong2*)&out[(size_t)row * Mm + mBase + mOff] = st;
    }
}

// ---------------- launch ----------------
extern "C" void kernel_launch(void* const* d_in, const int* in_sizes, int n_in,
                              void* d_out, int out_size) {
    const float *I = nullptr, *T = nullptr, *L = nullptr, *A = nullptr;
    for (int i = 0; i < n_in; i++) {
        switch (in_sizes[i]) {
            case Nn * Dd:      I = (const float*)d_in[i]; break;
            case 960:          T = (const float*)d_in[i]; break;
            case Mm * Cc * Kk: L = (const float*)d_in[i]; break;
            case Dd * Jj:      A = (const float*)d_in[i]; break;
            default: break;  // S, B unused — tree structure hardcoded
        }
    }
    float* out = (float*)d_out;

    cudaFuncSetAttribute(k_lut, cudaFuncAttributeMaxDynamicSharedMemorySize, K3_SMEM);

    dim3 g1(Jj / BN, Nn / BM);      // (2, 256)
    k_gemm_tree<<<g1, 256>>>(I, A, T);

    dim3 g0(32, 16), b0(32, 8);
    k_transpose<<<g0, b0>>>(L);

    dim3 g3(Mm / K3_MT, Nn / K3_ROWS);  // (16, 128)
    k_lut<<<g3, 256, K3_SMEM>>>(out);
}

// round 4
// speedup vs baseline: 1.2855x; 1.2855x over previous
#include <cuda_runtime.h>
#include <cuda_bf16.h>
#include <cstdint>

#define Nn 32768
#define Dd 512
#define Cc 64
#define Kk 16
#define Mm 512
#define Jj 256   // C*DEPTH

// ---------------- scratch ----------------
__device__ unsigned char d_idxT[Cc * Nn];          // [c][n]  2 MB
__device__ __nv_bfloat16 d_Lhi[Mm * Cc * Kk];      // [m][ck] 1 MB
__device__ __nv_bfloat16 d_Llo[Mm * Cc * Kk];      // [m][ck] 1 MB

// ---------------- K_split: L -> bf16 hi/lo ----------------
__global__ void k_split(const float* __restrict__ L) {
    int i = blockIdx.x * 256 + threadIdx.x;
    float f = L[i];
    __nv_bfloat16 h = __float2bfloat16(f);
    d_Lhi[i] = h;
    d_Llo[i] = __float2bfloat16(f - __bfloat162float(h));
}

// ---------------- K1: fused GEMM (P = I @ A) + tree traversal -> idxT ----------------
__device__ __forceinline__ unsigned trav(const float* __restrict__ Tc,
                                         float f0, float f1, float f2, float f3) {
    float f[4] = {f0, f1, f2, f3};
    unsigned node = 0, k = 0;
#pragma unroll
    for (int l = 0; l < 4; l++) {
        unsigned bit = (f[l] > __ldg(&Tc[node])) ? 1u : 0u;
        k = (k << 1) | bit;
        node = 2 * node + 1 + bit;
    }
    return k;
}

#define BM 128
#define BN 128
#define BK 32

__global__ __launch_bounds__(256) void k_gemm_tree(
    const float* __restrict__ I, const float* __restrict__ A,
    const float* __restrict__ T)
{
    __shared__ float Is[BK][132];
    __shared__ float As[BK][BN];

    int tid = threadIdx.x;
    int tx = tid & 15;
    int ty = tid >> 4;
    int rowBase = blockIdx.y * BM;
    int colBase = blockIdx.x * BN;

    int r  = tid >> 3;
    int kv = tid & 7;
    int kk = tid >> 5;
    int jv = tid & 31;

    unsigned long long acc[8][4];
#pragma unroll
    for (int i = 0; i < 8; i++)
#pragma unroll
        for (int j = 0; j < 4; j++) acc[i][j] = 0ull;

    for (int kt = 0; kt < Dd; kt += BK) {
#pragma unroll
        for (int q = 0; q < 4; q++) {
            int lr = r + q * 32;
            float4 v = *(const float4*)&I[(size_t)(rowBase + lr) * Dd + kt + kv * 4];
            Is[kv * 4 + 0][lr] = v.x;
            Is[kv * 4 + 1][lr] = v.y;
            Is[kv * 4 + 2][lr] = v.z;
            Is[kv * 4 + 3][lr] = v.w;
        }
#pragma unroll
        for (int q = 0; q < 4; q++)
            *(float4*)&As[kk + q * 8][jv * 4] =
                *(const float4*)&A[(size_t)(kt + kk + q * 8) * Jj + colBase + jv * 4];
        __syncthreads();

#pragma unroll 8
        for (int kx = 0; kx < BK; kx++) {
            float4 a01 = *(const float4*)&Is[kx][ty * 8];
            float4 a23 = *(const float4*)&Is[kx][ty * 8 + 4];
            ulonglong2 b0 = *(const ulonglong2*)&As[kx][tx * 4];
            ulonglong2 b1 = *(const ulonglong2*)&As[kx][64 + tx * 4];
            unsigned long long bp[4] = {b0.x, b0.y, b1.x, b1.y};
            float av[8] = {a01.x, a01.y, a01.z, a01.w, a23.x, a23.y, a23.z, a23.w};
#pragma unroll
            for (int i = 0; i < 8; i++) {
                unsigned long long ap;
                asm("mov.b64 %0, {%1, %2};" : "=l"(ap) : "f"(av[i]), "f"(av[i]));
#pragma unroll
                for (int j = 0; j < 4; j++)
                    asm("fma.rn.f32x2 %0, %1, %2, %0;"
                        : "+l"(acc[i][j]) : "l"(ap), "l"(bp[j]));
            }
        }
        __syncthreads();
    }

    int cbBase = colBase >> 2;
    int cb0 = cbBase + tx;
    int cb1 = cbBase + 16 + tx;
    unsigned long long p0 = 0, p1 = 0;
#pragma unroll
    for (int i = 0; i < 8; i++) {
        float f[8];
#pragma unroll
        for (int j = 0; j < 4; j++)
            asm("mov.b64 {%0, %1}, %2;" : "=f"(f[2 * j]), "=f"(f[2 * j + 1]) : "l"(acc[i][j]));
        unsigned k1 = trav(&T[cb0 * 15], f[0], f[1], f[2], f[3]);
        unsigned k2 = trav(&T[cb1 * 15], f[4], f[5], f[6], f[7]);
        p0 |= (unsigned long long)k1 << (8 * i);
        p1 |= (unsigned long long)k2 << (8 * i);
    }
    int nb = rowBase + ty * 8;
    *(unsigned long long*)&d_idxT[(size_t)cb0 * Nn + nb] = p0;
    *(unsigned long long*)&d_idxT[(size_t)cb1 * Nn + nb] = p1;
}

// ---------------- K2: mma.sync bf16 one-hot GEMM  out = E @ (Lhi + Llo) ----------------
// Grid: x = 16 m-tiles (32 m each), y = 8 n-splits (4096 n each).
// CTA: 256 threads = 8 warps. Warp w handles n16 = w-th 16 rows of the 128-row iter,
// all 32 m of the CTA tile (4 m-slices of 8).
// B (Lhi & Llo for the 32-m tile, full K=1024 each) resident in smem for the CTA.
// A fragment synthesized from idx bytes (one-hot), one A frag per k16 chunk,
// reused for 4 m-slices x {hi,lo} = 8 HMMAs.

#define BSTRIDE 1032                       // bf16 elements per m-row (padded)
#define S2_BH   0
#define S2_BL   (32 * BSTRIDE * 2)         // 66048
#define S2_IDX  (2 * 32 * BSTRIDE * 2)     // 132096
#define S2_SMEM (S2_IDX + Cc * 128)        // 140288

#define NSPLIT 8
#define NPER   (Nn / NSPLIT)               // 4096

__global__ __launch_bounds__(256) void k_lutmma(float* __restrict__ out)
{
    extern __shared__ char sm[];
    __nv_bfloat16* Bh = (__nv_bfloat16*)(sm + S2_BH);
    __nv_bfloat16* Bl = (__nv_bfloat16*)(sm + S2_BL);
    unsigned char* idxs = (unsigned char*)(sm + S2_IDX);

    int tid  = threadIdx.x;
    int wid  = tid >> 5;
    int lane = tid & 31;
    int g    = lane >> 2;      // group 0..7
    int t4   = lane & 3;

    int mBase = blockIdx.x * 32;
    int nRange = blockIdx.y * NPER;

    // ---- load B tiles once: 32 m-rows x 1024 k, hi and lo ----
    // 32 rows x 128 uint4 (8 bf16) each = 4096 uint4 per matrix
    for (int i = tid; i < 32 * 128; i += 256) {
        int m = i >> 7, k8 = (i & 127) * 8;
        Bh[m * BSTRIDE + k8 + 0] = d_Lhi[(size_t)(mBase + m) * 1024 + k8];  // placeholder
    }
    // (redo with vector loads for real)
    __syncthreads();
    for (int i = tid; i < 32 * 128; i += 256) {
        int m = i >> 7, k8 = (i & 127) * 8;
        *(uint4*)&Bh[m * BSTRIDE + k8] = *(const uint4*)&d_Lhi[(size_t)(mBase + m) * 1024 + k8];
        *(uint4*)&Bl[m * BSTRIDE + k8] = *(const uint4*)&d_Llo[(size_t)(mBase + m) * 1024 + k8];
    }
    __syncthreads();

    int n0loc = wid * 16 + g;    // local n row (0..127) for A row g
    for (int it = 0; it < NPER / 128; it++) {
        int nb = nRange + it * 128;
        // ---- load idx tile: 64 c x 128 n bytes ----
        {
            int c = tid >> 2, off = (tid & 3) * 32;
            *(uint4*)&idxs[c * 128 + off] =
                *(const uint4*)&d_idxT[(size_t)c * Nn + nb + off];
            *(uint4*)&idxs[c * 128 + off + 16] =
                *(const uint4*)&d_idxT[(size_t)c * Nn + nb + off + 16];
        }
        __syncthreads();

        float acc[4][4];
#pragma unroll
        for (int ms = 0; ms < 4; ms++)
#pragma unroll
            for (int q = 0; q < 4; q++) acc[ms][q] = 0.f;

#pragma unroll 4
        for (int c = 0; c < Cc; c++) {
            unsigned i0 = idxs[c * 128 + n0loc];
            unsigned i1 = idxs[c * 128 + n0loc + 8];
            unsigned s0 = 0x3F80u << ((i0 & 1) << 4);
            unsigned s1 = 0x3F80u << ((i1 & 1) << 4);
            unsigned h0 = i0 >> 1, h1 = i1 >> 1;
            unsigned a0 = (h0 == (unsigned)t4)     ? s0 : 0u;
            unsigned a1 = (h1 == (unsigned)t4)     ? s1 : 0u;
            unsigned a2 = (h0 == (unsigned)t4 + 4) ? s0 : 0u;
            unsigned a3 = (h1 == (unsigned)t4 + 4) ? s1 : 0u;

#pragma unroll
            for (int ms = 0; ms < 4; ms++) {
                const __nv_bfloat16* bh = &Bh[(ms * 8 + g) * BSTRIDE + c * 16 + t4 * 2];
                const __nv_bfloat16* bl = &Bl[(ms * 8 + g) * BSTRIDE + c * 16 + t4 * 2];
                unsigned bh0 = *(const unsigned*)bh;
                unsigned bh1 = *(const unsigned*)(bh + 8);
                unsigned bl0 = *(const unsigned*)bl;
                unsigned bl1 = *(const unsigned*)(bl + 8);
                asm volatile(
                    "mma.sync.aligned.m16n8k16.row.col.f32.bf16.bf16.f32 "
                    "{%0,%1,%2,%3}, {%4,%5,%6,%7}, {%8,%9}, {%0,%1,%2,%3};"
                    : "+f"(acc[ms][0]), "+f"(acc[ms][1]), "+f"(acc[ms][2]), "+f"(acc[ms][3])
                    : "r"(a0), "r"(a1), "r"(a2), "r"(a3), "r"(bh0), "r"(bh1));
                asm volatile(
                    "mma.sync.aligned.m16n8k16.row.col.f32.bf16.bf16.f32 "
                    "{%0,%1,%2,%3}, {%4,%5,%6,%7}, {%8,%9}, {%0,%1,%2,%3};"
                    : "+f"(acc[ms][0]), "+f"(acc[ms][1]), "+f"(acc[ms][2]), "+f"(acc[ms][3])
                    : "r"(a0), "r"(a1), "r"(a2), "r"(a3), "r"(bl0), "r"(bl1));
            }
        }

        // ---- store: rows nb + wid*16 + g and +8 ----
        int nA = nb + n0loc;
#pragma unroll
        for (int ms = 0; ms < 4; ms++) {
            float2 v0 = make_float2(acc[ms][0], acc[ms][1]);
            float2 v1 = make_float2(acc[ms][2], acc[ms][3]);
            *(float2*)&out[(size_t)nA * Mm + mBase + ms * 8 + t4 * 2] = v0;
            *(float2*)&out[(size_t)(nA + 8) * Mm + mBase + ms * 8 + t4 * 2] = v1;
        }
        __syncthreads();
    }
}

// ---------------- launch ----------------
extern "C" void kernel_launch(void* const* d_in, const int* in_sizes, int n_in,
                              void* d_out, int out_size) {
    const float *I = nullptr, *T = nullptr, *L = nullptr, *A = nullptr;
    for (int i = 0; i < n_in; i++) {
        switch (in_sizes[i]) {
            case Nn * Dd:      I = (const float*)d_in[i]; break;
            case 960:          T = (const float*)d_in[i]; break;
            case Mm * Cc * Kk: L = (const float*)d_in[i]; break;
            case Dd * Jj:      A = (const float*)d_in[i]; break;
            default: break;  // S, B unused — tree structure hardcoded
        }
    }
    float* out = (float*)d_out;

    cudaFuncSetAttribute(k_lutmma, cudaFuncAttributeMaxDynamicSharedMemorySize, S2_SMEM);

    k_split<<<(Mm * Cc * Kk) / 256, 256>>>(L);

    dim3 g1(Jj / BN, Nn / BM);      // (2, 256)
    k_gemm_tree<<<g1, 256>>>(I, A, T);

    dim3 g2(Mm / 32, NSPLIT);       // (16, 8)
    k_lutmma<<<g2, 256, S2_SMEM>>>(out);
}